// round 13
// baseline (speedup 1.0000x reference)
#include <cuda_runtime.h>

// NonMaximaSuppression2d: x (8,32,512,512) fp32.
// m = max over 8 neighbors (replicate pad), floored at 0 (zeroed center tap).
// out = x * (x > m).
// R12: extrapolate the MLP axis (R9 proved MLP > occupancy; R11/R12 proved
// reg caps that break the batch lose). RPT=8, 10-row vector front-batch
// (40 regs of batch), launch_bounds(128,9) = 56-reg cap, 9 CTAs/SM:
// outstanding loads/SM 9*4*10=360 vs R9's 288. Edge scalars deferred to
// consume time (L1 hits on warp-resident lines, minimal live range).

#define HH 512
#define WW 512
#define RPT 8           // rows per output strip
#define NROWS (RPT + 2) // 10 rows in the window
#define TPB 128         // threads per block = WW/4 float4 groups

__device__ __forceinline__ int clampy(int y) { return min(max(y, 0), HH - 1); }

// max of 3 horizontally adjacent values per lane (rows above/below)
__device__ __forceinline__ float4 hmax3(const float4& v, float l, float r) {
    float4 h;
    h.x = fmaxf(fmaxf(l,   v.x), v.y);
    h.y = fmaxf(fmaxf(v.x, v.y), v.z);
    h.z = fmaxf(fmaxf(v.y, v.z), v.w);
    h.w = fmaxf(fmaxf(v.z, v.w), r);
    return h;
}

// max of the 2 horizontal neighbors (center excluded; for the center row)
__device__ __forceinline__ float4 hmax2(const float4& v, float l, float r) {
    float4 h;
    h.x = fmaxf(l,   v.y);
    h.y = fmaxf(v.x, v.z);
    h.z = fmaxf(v.y, v.w);
    h.w = fmaxf(v.z, r);
    return h;
}

__global__ __launch_bounds__(TPB, 9)
void nms2d_kernel(const float* __restrict__ x, float* __restrict__ out) {
    const int tiles_per_img = HH / RPT;             // 64
    const int img  = blockIdx.x / tiles_per_img;
    const int tile = blockIdx.x % tiles_per_img;

    const float* in = x   + (size_t)img * HH * WW;
    float*       o  = out + (size_t)img * HH * WW;

    const int c  = threadIdx.x * 4;                 // 0..508
    const int y0 = tile * RPT;

    // front-batch: 10 independent vector LDG.128, nothing else before them
    float4 v[NROWS];
    #pragma unroll
    for (int k = 0; k < NROWS; k++)
        v[k] = *reinterpret_cast<const float4*>(
            in + (size_t)clampy(y0 - 1 + k) * WW + c);

    float* op = o + (size_t)y0 * WW + c;

    #pragma unroll
    for (int i = 0; i < RPT; i++) {
        // edge scalars at consume time: L1 hits (lines warp-resident from
        // the batch), transient registers only
        const float* pp = in + (size_t)clampy(y0 - 1 + i) * WW + c;
        const float* pc = in + (size_t)(y0 + i) * WW + c;
        const float* pn = in + (size_t)clampy(y0 + i + 1) * WW + c;
        float lp = (c > 0)      ? __ldg(pp - 1) : v[i].x;
        float rp = (c + 4 < WW) ? __ldg(pp + 4) : v[i].w;
        float lc = (c > 0)      ? __ldg(pc - 1) : v[i + 1].x;
        float rc = (c + 4 < WW) ? __ldg(pc + 4) : v[i + 1].w;
        float ln = (c > 0)      ? __ldg(pn - 1) : v[i + 2].x;
        float rn = (c + 4 < WW) ? __ldg(pn + 4) : v[i + 2].w;

        float4 mp = hmax3(v[i],     lp, rp);
        float4 mc = hmax2(v[i + 1], lc, rc);
        float4 mn = hmax3(v[i + 2], ln, rn);

        // fold the zeroed-center-tap floor (reference inits max at 0)
        float4 m;
        m.x = fmaxf(fmaxf(fmaxf(mp.x, mc.x), mn.x), 0.0f);
        m.y = fmaxf(fmaxf(fmaxf(mp.y, mc.y), mn.y), 0.0f);
        m.z = fmaxf(fmaxf(fmaxf(mp.z, mc.z), mn.z), 0.0f);
        m.w = fmaxf(fmaxf(fmaxf(mp.w, mc.w), mn.w), 0.0f);

        float4 xc = v[i + 1];
        float4 rr;
        rr.x = (xc.x > m.x) ? xc.x : 0.0f;
        rr.y = (xc.y > m.y) ? xc.y : 0.0f;
        rr.z = (xc.z > m.z) ? xc.z : 0.0f;
        rr.w = (xc.w > m.w) ? xc.w : 0.0f;

        *reinterpret_cast<float4*>(op) = rr;
        op += WW;
    }
}

extern "C" void kernel_launch(void* const* d_in, const int* in_sizes, int n_in,
                              void* d_out, int out_size) {
    const float* x = (const float*)d_in[0];
    float* out = (float*)d_out;

    const int n_img = in_sizes[0] / (HH * WW);      // B*C = 256
    const int blocks = n_img * (HH / RPT);          // 16384

    nms2d_kernel<<<blocks, TPB>>>(x, out);
}

// round 14
// speedup vs baseline: 1.6313x; 1.6313x over previous
#include <cuda_runtime.h>

// NonMaximaSuppression2d: x (8,32,512,512) fp32.
// m = max over 8 neighbors (replicate pad), floored at 0 (zeroed center tap).
// out = x * (x > m).
// FINAL (= R9, the measured optimum of the explored config space):
//   RPT=4, 6-row window fully front-batched (6 independent LDG.128 + edge
//   scalars riding the same in-flight lines), launch_bounds(128,12) -> regs=40,
//   12 CTAs/SM, outstanding loads/SM ~288, plain write-back stores.
// Measured: 76.2us ncu / 80.4us wall, 6346 GB/s (80.1% DRAM), traffic at the
// ~490MB read+write floor. Neighboring configs all measured worse:
//   RPT {32,16,8,4,2} -> {86.0,87.2,79.4,78.0,84.9}us ncu (at 32-reg cfg)
//   shuffle halos: issue 55%, regression; deferred strided halos: L1 90%, 134us
//   13-CTA (39-reg) cap: batch serialized, regression; __stcs vs plain: neutral.

#define HH 512
#define WW 512
#define RPT 4           // rows per output strip
#define NROWS (RPT + 2) // 6 rows in the window
#define TPB 128         // threads per block = WW/4 float4 groups

struct RowRegs {
    float4 v;   // 4 center values
    float  l;   // value at col-1 (replicated at left edge)
    float  r;   // value at col+4 (replicated at right edge)
};

__device__ __forceinline__ void load_row(const float* __restrict__ img,
                                         int y, int c, RowRegs& rr) {
    int yc = min(max(y, 0), HH - 1);
    const float* p = img + (size_t)yc * WW + c;
    rr.v = *reinterpret_cast<const float4*>(p);
    // edge scalars hit the same 128B lines as neighbor lanes' vectors -> L1
    rr.l = (c > 0)      ? __ldg(p - 1) : rr.v.x;
    rr.r = (c + 4 < WW) ? __ldg(p + 4) : rr.v.w;
}

// max of 3 horizontally adjacent values per lane (rows above/below)
__device__ __forceinline__ float4 hmax3(const RowRegs& rr) {
    float4 h;
    h.x = fmaxf(fmaxf(rr.l,   rr.v.x), rr.v.y);
    h.y = fmaxf(fmaxf(rr.v.x, rr.v.y), rr.v.z);
    h.z = fmaxf(fmaxf(rr.v.y, rr.v.z), rr.v.w);
    h.w = fmaxf(fmaxf(rr.v.z, rr.v.w), rr.r);
    return h;
}

// max of the 2 horizontal neighbors (center excluded; for the center row)
__device__ __forceinline__ float4 hmax2(const RowRegs& rr) {
    float4 h;
    h.x = fmaxf(rr.l,   rr.v.y);
    h.y = fmaxf(rr.v.x, rr.v.z);
    h.z = fmaxf(rr.v.y, rr.v.w);
    h.w = fmaxf(rr.v.z, rr.r);
    return h;
}

__global__ __launch_bounds__(TPB, 12)
void nms2d_kernel(const float* __restrict__ x, float* __restrict__ out) {
    const int tiles_per_img = HH / RPT;             // 128
    const int img  = blockIdx.x / tiles_per_img;
    const int tile = blockIdx.x % tiles_per_img;

    const float* in = x   + (size_t)img * HH * WW;
    float*       o  = out + (size_t)img * HH * WW;

    const int c  = threadIdx.x * 4;                 // 0..508
    const int y0 = tile * RPT;

    // front-batch the entire 6-row window: 6 independent LDG.128 (+ edge
    // scalars interleaved, riding the same in-flight lines)
    RowRegs w[NROWS];
    #pragma unroll
    for (int k = 0; k < NROWS; k++)
        load_row(in, y0 - 1 + k, c, w[k]);

    float* op = o + (size_t)y0 * WW + c;

    #pragma unroll
    for (int i = 0; i < RPT; i++) {
        float4 mp = hmax3(w[i]);
        float4 mc = hmax2(w[i + 1]);
        float4 mn = hmax3(w[i + 2]);

        // fold the zeroed-center-tap floor (reference inits max at 0)
        float4 m;
        m.x = fmaxf(fmaxf(fmaxf(mp.x, mc.x), mn.x), 0.0f);
        m.y = fmaxf(fmaxf(fmaxf(mp.y, mc.y), mn.y), 0.0f);
        m.z = fmaxf(fmaxf(fmaxf(mp.z, mc.z), mn.z), 0.0f);
        m.w = fmaxf(fmaxf(fmaxf(mp.w, mc.w), mn.w), 0.0f);

        float4 xc = w[i + 1].v;
        float4 r;
        r.x = (xc.x > m.x) ? xc.x : 0.0f;
        r.y = (xc.y > m.y) ? xc.y : 0.0f;
        r.z = (xc.z > m.z) ? xc.z : 0.0f;
        r.w = (xc.w > m.w) ? xc.w : 0.0f;

        *reinterpret_cast<float4*>(op) = r;
        op += WW;
    }
}

extern "C" void kernel_launch(void* const* d_in, const int* in_sizes, int n_in,
                              void* d_out, int out_size) {
    const float* x = (const float*)d_in[0];
    float* out = (float*)d_out;

    const int n_img = in_sizes[0] / (HH * WW);      // B*C = 256
    const int blocks = n_img * (HH / RPT);          // 32768

    nms2d_kernel<<<blocks, TPB>>>(x, out);
}